// round 7
// baseline (speedup 1.0000x reference)
#include <cuda_runtime.h>
#include <math.h>

#define BB 64
#define NTOK 2304
#define DD 64
#define NHEADS 8
#define TOKENS (BB*NTOK)   // 147456

// ---------------- scratch (device globals; no allocations) ----------------
__device__ float g_xn[TOKENS*DD];                // TRANSPOSED: [d][token]  (d*TOKENS + token)
__device__ float g_v[TOKENS*DD];                 // head-major: [(b*8+h)*2304 + p]*8 + j
__device__ float g_logits[BB*NHEADS*NTOK];
__device__ float g_cls[(size_t)TOKENS*4*DD];     // [tok][r][64e]
__device__ float g_WL[NHEADS*DD];
__device__ float g_bL[NHEADS];
__device__ float g_vc[DD];
__device__ float g_clslogit[NHEADS];
__device__ float g_cvec[DD];
__device__ float g_cvecp[NHEADS*DD];             // per-head bwproj fold
__device__ float4 g_P4p[NHEADS*1024];   // [h][f2][lane] = (P2[2f2][l],P2[2f2][l+32],P2[2f2+1][l],P2[2f2+1][l+32])
__device__ float4 g_Q4p[NHEADS*1024];   // [h][e2][lane] = (Q2[2e2][l],Q2[2e2][l+32],Q2[2e2+1][l],Q2[2e2+1][l+32])
__device__ float g_u2[NHEADS*DD];

__device__ __forceinline__ float kscale() { return 0.35355339059327373f; } // 8^-0.5

// ---------------- f32x2 helpers ----------------
typedef unsigned long long ull;
__device__ __forceinline__ ull pack2(float x, float y) {
    ull r; asm("mov.b64 %0, {%1,%2};" : "=l"(r) : "f"(x), "f"(y)); return r;
}
__device__ __forceinline__ void unpack2(ull v, float& x, float& y) {
    asm("mov.b64 {%0,%1}, %2;" : "=f"(x), "=f"(y) : "l"(v));
}
__device__ __forceinline__ void ffma2(ull& acc, ull a, ull b) {
    asm("fma.rn.f32x2 %0, %1, %2, %0;" : "+l"(acc) : "l"(a), "l"(b));
}

#define SBUF 4160   // padded 64x64 buffer (allows 65-stride layouts)

// ---------------- single precompute kernel: 17 blocks ----------------
__global__ void __launch_bounds__(256) precomp(
    const float* __restrict__ cls_tok,
    const float* __restrict__ Wwqkv, const float* __restrict__ bwqkv,
    const float* __restrict__ brao,
    const float* __restrict__ Wout, const float* __restrict__ bout,
    const float* __restrict__ Wraq, const float* __restrict__ Wrak,
    const float* __restrict__ Wrao, const float* __restrict__ Wrav,
    const float* __restrict__ Wqkv, const float* __restrict__ bqkv,
    const float* __restrict__ Wwproj, const float* __restrict__ bwproj)
{
    extern __shared__ float s[];
    float* s0 = s;
    float* s1 = s + SBUF;
    float* s2 = s + 2*SBUF;
    int bid = blockIdx.x, tid = threadIdx.x;

    if (bid == 0) {
        __shared__ float scq[192];
        __shared__ float sqc[64];
        __shared__ float sred[256];
        if (tid < 192) {
            float a = bwqkv[tid];
            for (int d = 0; d < 64; d++) a += Wwqkv[tid*64+d]*cls_tok[d];
            scq[tid] = a;
        }
        __syncthreads();
        if (tid < 64) { sqc[tid] = scq[tid]*kscale(); g_vc[tid] = scq[128+tid]; }
        __syncthreads();
        if (tid < 8) {
            float cl = 0.f, bl = 0.f;
            for (int j = 0; j < 8; j++) {
                cl += sqc[tid*8+j]*scq[64+tid*8+j];
                bl += sqc[tid*8+j]*bwqkv[64+tid*8+j];
            }
            g_clslogit[tid] = cl; g_bL[tid] = bl;
        }
        for (int i = tid; i < 512; i += 256) {
            int h = i>>6, d = i&63;
            float a = 0.f;
            for (int j = 0; j < 8; j++) a += sqc[h*8+j]*Wwqkv[(64+h*8+j)*64+d];
            g_WL[i] = a;
        }
        {
            int o = tid>>2, q = tid&3;
            float a = (q==0) ? bout[o] : 0.f;
            for (int k = q*128; k < q*128+128; k++) a += Wout[o*512+k]*brao[k&63];
            sred[tid] = a;
        }
        __syncthreads();
        if (tid < 64)
            g_cvec[tid] = sred[4*tid] + sred[4*tid+1] + sred[4*tid+2] + sred[4*tid+3];
    }
    else if (bid <= 8) {
        // ---- P side: G = Wraq^T Wrak ; P = scale*Wq_h^T G ; P2 = P Wwproj ----
        int h = bid - 1;
        __shared__ float su[64];
        for (int i = tid; i < 4096; i += 256) { s0[i] = Wraq[i]; s1[i] = Wrak[i]; }
        __syncthreads();
        for (int i = tid; i < 4096; i += 256) {           // G[dd][g] -> s2
            int dd = i>>6, g = i&63;
            float a = 0.f;
            #pragma unroll 8
            for (int e = 0; e < 64; e++) a += s0[e*64+dd]*s1[e*64+g];
            s2[i] = a;
        }
        __syncthreads();
        for (int i = tid; i < 4096; i += 256) s0[i] = Wqkv[h*4096 + i];   // Wq[dd][f]
        __syncthreads();
        for (int i = tid; i < 4096; i += 256) {           // P[f][g] -> s1
            int f = i>>6, g = i&63;
            float a = 0.f;
            #pragma unroll 8
            for (int dd = 0; dd < 64; dd++) a += s0[dd*64+f]*s2[dd*64+g];
            s1[i] = a*kscale();
        }
        if (tid < 64) {                                    // u[g]
            float a = 0.f;
            for (int dd = 0; dd < 64; dd++) a += bqkv[h*64+dd]*s2[dd*64+tid];
            su[tid] = a*kscale();
        }
        __syncthreads();
        for (int i = tid; i < 4096; i += 256) s0[i] = Wwproj[i];   // W[g][e]
        __syncthreads();
        for (int i = tid; i < 4096; i += 256) {           // P2[f][e] -> s2
            int f = i>>6, e = i&63;
            float a = 0.f;
            #pragma unroll 8
            for (int g = 0; g < 64; g++) a += s1[f*64+g]*s0[g*64+e];
            s2[i] = a;
        }
        if (tid < 64) {                                    // u2[e]
            float a = 0.f;
            for (int g = 0; g < 64; g++) a += su[g]*s0[g*64+tid];
            g_u2[h*64+tid] = a;
        }
        __syncthreads();
        for (int i = tid; i < 1024; i += 256) {            // pack
            int k2 = i>>5, l = i&31;
            g_P4p[h*1024+i] = make_float4(s2[(2*k2)*64+l],   s2[(2*k2)*64+l+32],
                                          s2[(2*k2+1)*64+l], s2[(2*k2+1)*64+l+32]);
        }
    }
    else {
        // ---- Q side: R = Wrao Wrav ; Q_h = Wout_h R ; Q2 = Wwproj^T Q ----
        int h = bid - 9;
        for (int i = tid; i < 4096; i += 256) { s0[i] = Wrao[i]; s1[i] = Wrav[i]; }
        __syncthreads();
        for (int i = tid; i < 4096; i += 256) {           // R[a][g] -> s2
            int a_ = i>>6, g = i&63;
            float a = 0.f;
            #pragma unroll 8
            for (int c = 0; c < 64; c++) a += s0[a_*64+c]*s1[c*64+g];
            s2[i] = a;
        }
        __syncthreads();
        for (int i = tid; i < 4096; i += 256) {           // Wout_h[o][a]
            int o = i>>6, a_ = i&63;
            s0[i] = Wout[o*512 + h*64 + a_];
        }
        __syncthreads();
        for (int i = tid; i < 4096; i += 256) {           // Qt[o][g] -> s1
            int o = i>>6, g = i&63;
            float a = 0.f;
            #pragma unroll 8
            for (int a_ = 0; a_ < 64; a_++) a += s0[o*64+a_]*s2[a_*64+g];
            s1[i] = a;
        }
        __syncthreads();
        if (tid < 64) {                                    // cvecp[h][o]
            float a = 0.f;
            for (int g = 0; g < 64; g++) a += bwproj[g]*s1[tid*64+g];
            g_cvecp[h*64+tid] = a;
        }
        for (int i = tid; i < 4096; i += 256) s0[i] = Wwproj[i];   // W[g][e]
        __syncthreads();
        for (int i = tid; i < 4096; i += 256) {           // Q2t[o][e] -> s2 (65-stride)
            int o = i>>6, e = i&63;
            float a = 0.f;
            #pragma unroll 8
            for (int g = 0; g < 64; g++) a += s0[g*64+e]*s1[o*64+g];
            s2[o*65+e] = a;
        }
        __syncthreads();
        for (int i = tid; i < 1024; i += 256) {            // pack: Q2[e][o] = s2[o*65+e]
            int k2 = i>>5, l = i&31;
            g_Q4p[h*1024+i] = make_float4(s2[l*65 + 2*k2],      s2[(l+32)*65 + 2*k2],
                                          s2[l*65 + 2*k2 + 1],  s2[(l+32)*65 + 2*k2 + 1]);
        }
    }
}

// ---------------- K1: LayerNorm + logits + v projection (64 tokens/block) ----------------
// writes g_xn TRANSPOSED [d][token] via a 64x65 smem tile
__global__ void __launch_bounds__(256) k_ln(const float* __restrict__ x,
     const float* __restrict__ ln_g, const float* __restrict__ ln_b,
     const float* __restrict__ Wwqkv, const float* __restrict__ bwqkv)
{
    __shared__ float sfv[64*66];     // pairs (Wwv[e][d], Wwv[e+32][d]) at [d*66 + 2*(e&31) + (e>>5)]
    __shared__ float sWL[8*65];
    __shared__ float sxb[8*64];
    __shared__ float sxt[64*65];     // transpose tile [d][t]
    int tid = threadIdx.x, warp = tid>>5, lane = tid&31;
    for (int i = tid; i < 4096; i += 256) {
        int e = i>>6, d = i&63;
        sfv[d*66 + 2*(e&31) + (e>>5)] = Wwqkv[8192 + i];
    }
    for (int i = tid; i < 512; i += 256)
        sWL[(i>>6)*65 + (i&63)] = g_WL[i];
    __syncthreads();
    float ga0 = ln_g[lane], ga1 = ln_g[lane+32];
    float gb0 = ln_b[lane], gb1 = ln_b[lane+32];
    float bv0 = bwqkv[128+lane], bv1 = bwqkv[128+lane+32];
    int tok_base = blockIdx.x*64 + warp*8;
    int b = tok_base/NTOK;
    int hh = lane>>2, qq = lane&3;
    for (int t = 0; t < 8; t++) {
        int token = tok_base + t;
        float x0 = x[token*64 + lane];
        float x1 = x[token*64 + lane + 32];
        float s = x0 + x1, ss = x0*x0 + x1*x1;
        #pragma unroll
        for (int off = 16; off; off >>= 1) {
            s  += __shfl_xor_sync(0xffffffffu, s,  off);
            ss += __shfl_xor_sync(0xffffffffu, ss, off);
        }
        float mu = s*(1.f/64.f);
        float var = ss*(1.f/64.f) - mu*mu;
        float rstd = rsqrtf(var + 1e-5f);
        float xn0 = (x0-mu)*rstd*ga0 + gb0;
        float xn1 = (x1-mu)*rstd*ga1 + gb1;
        int tcol = warp*8 + t;
        sxt[lane*65 + tcol]      = xn0;
        sxt[(lane+32)*65 + tcol] = xn1;
        sxb[warp*64+lane] = xn0; sxb[warp*64+lane+32] = xn1;
        __syncwarp();
        ull acc = pack2(bv0, bv1);
        #pragma unroll 8
        for (int d = 0; d < 64; d++) {
            float xd = sxb[warp*64+d];
            float2 w = *(const float2*)(sfv + d*66 + 2*lane);
            ffma2(acc, pack2(xd, xd), pack2(w.x, w.y));
        }
        float v0, v1; unpack2(acc, v0, v1);
        int nn = token - b*NTOK;
        {
            int h0 = lane>>3, j0 = lane&7;
            g_v[((size_t)(b*8+h0)*NTOK + nn)*8 + j0] = v0;
            int h1 = (lane+32)>>3;
            g_v[((size_t)(b*8+h1)*NTOK + nn)*8 + j0] = v1;
        }
        {
            float a = 0.f;
            #pragma unroll
            for (int dd = 0; dd < 16; dd++)
                a += sxb[warp*64 + qq*16 + dd]*sWL[hh*65 + qq*16 + dd];
            a += __shfl_xor_sync(0xffffffffu, a, 1);
            a += __shfl_xor_sync(0xffffffffu, a, 2);
            if (qq == 0) g_logits[(b*8+hh)*NTOK + nn] = a + g_bL[hh];
        }
        __syncwarp();
    }
    __syncthreads();
    // coalesced transposed write: rows of 64 floats
    int tok0 = blockIdx.x*64;
    for (int i = tid; i < 4096; i += 256) {
        int d = i>>6, t = i&63;
        g_xn[(size_t)d*TOKENS + tok0 + t] = sxt[d*65 + t];
    }
}

// ---------------- K2: max + exp + integral-image quad sums + cls_out ----------------
#define QCH 2352   // 48*49
__global__ void __launch_bounds__(512) k_quad()
{
    extern __shared__ float s[];  // 9 * 2352 floats
    __shared__ float red[512];
    __shared__ float smv;
    int bid = blockIdx.x, tid = threadIdx.x;
    int b = bid>>3, h = bid&7;
    for (int p = tid; p < 2304; p += 512) {
        int y = p/48, xx = p - y*48;
        s[y*49+xx] = g_logits[bid*NTOK + p];
    }
    __syncthreads();
    float mloc = -1e30f;
    for (int p = tid; p < 2304; p += 512) {
        int y = p/48, xx = p - y*48;
        mloc = fmaxf(mloc, s[y*49+xx]);
    }
    red[tid] = mloc;
    __syncthreads();
    for (int st = 256; st; st >>= 1) {
        if (tid < st) red[tid] = fmaxf(red[tid], red[tid+st]);
        __syncthreads();
    }
    if (tid == 0) smv = fmaxf(red[0], g_clslogit[h]);
    __syncthreads();
    float m = smv;
    float ecls = __expf(g_clslogit[h] - m);
    for (int p = tid; p < 2304; p += 512) {
        int y = p/48, xx = p - y*48;
        int idx = y*49+xx;
        s[idx] = __expf(s[idx] - m);
    }
    __syncthreads();
    const float* vbase = g_v + (size_t)bid*NTOK*8;
    for (int i = tid; i < 2304*8; i += 512) {
        int p = i>>3, j = i&7;
        int y = p/48, xx = p - y*48;
        s[(1+j)*QCH + y*49+xx] = s[y*49+xx] * vbase[i];
    }
    __syncthreads();
    for (int sid = tid; sid < 432; sid += 512) {
        int ch = sid/48, y = sid - (sid/48)*48;
        float* row = s + ch*QCH + y*49;
        float a = 0.f;
        #pragma unroll 8
        for (int xx = 0; xx < 48; xx++) { a += row[xx]; row[xx] = a; }
    }
    __syncthreads();
    for (int sid = tid; sid < 432; sid += 512) {
        int ch = sid/48, xx = sid - (sid/48)*48;
        float* col = s + ch*QCH + xx;
        float a = 0.f;
        #pragma unroll 8
        for (int y = 0; y < 48; y++) { a += col[y*49]; col[y*49] = a; }
    }
    __syncthreads();
    float vc[8];
    #pragma unroll
    for (int j = 0; j < 8; j++) vc[j] = g_vc[h*8+j];
    for (int p = tid; p < 2304; p += 512) {
        int y = p/48, xx = p - y*48;
        int iC  = y*49 + xx;
        int iRT = y*49 + 47;
        int iCB = 47*49 + xx;
        int iT  = 47*49 + 47;
        int iCm = iC - 1;
        int iUp = iC - 49;
        int iUR = iRT - 49;
        int iCL = iCB - 1;
        int iUL = iUp - 1;
        bool hx = xx > 0, hy = y > 0;
        float rd[4];
        {
            const float* C = s;
            float tl = C[iC];
            float tr = C[iRT] - (hx ? C[iCm] : 0.f);
            float bl = C[iCB] - (hy ? C[iUp] : 0.f);
            float br = C[iT] - (hy ? C[iUR] : 0.f) - (hx ? C[iCL] : 0.f) + ((hx&&hy) ? C[iUL] : 0.f);
            rd[0] = 1.f/(ecls+tl); rd[1] = 1.f/(ecls+tr);
            rd[2] = 1.f/(ecls+bl); rd[3] = 1.f/(ecls+br);
        }
        float out[4][8];
        #pragma unroll
        for (int j = 0; j < 8; j++) {
            const float* C = s + (1+j)*QCH;
            float tl = C[iC];
            float tr = C[iRT] - (hx ? C[iCm] : 0.f);
            float bl = C[iCB] - (hy ? C[iUp] : 0.f);
            float br = C[iT] - (hy ? C[iUR] : 0.f) - (hx ? C[iCL] : 0.f) + ((hx&&hy) ? C[iUL] : 0.f);
            float base = ecls*vc[j];
            out[0][j] = (base+tl)*rd[0];
            out[1][j] = (base+tr)*rd[1];
            out[2][j] = (base+bl)*rd[2];
            out[3][j] = (base+br)*rd[3];
        }
        float* op = g_cls + ((size_t)(b*NTOK + p)*4)*64 + h*8;
        #pragma unroll
        for (int r = 0; r < 4; r++) {
            float4 v0 = make_float4(out[r][0], out[r][1], out[r][2], out[r][3]);
            float4 v1 = make_float4(out[r][4], out[r][5], out[r][6], out[r][7]);
            *(float4*)(op + r*64)     = v0;
            *(float4*)(op + r*64 + 4) = v1;
        }
    }
}

// ---------------- K3: fused epilogue — 4 warps, 16 tokens/warp, single weight buffer ----
#define XS 68
__global__ void __launch_bounds__(128, 4) k_epi(float* __restrict__ outp)
{
    extern __shared__ float s[];
    float*  scmix = s;                        // [64 e][XS]
    float4* ws    = (float4*)(s + 64*XS);     // [32 k2][32 lane], reused P then Q
    __shared__ float scv[64];
    int tid = threadIdx.x, warp = tid>>5, lane = tid&31;
    int tok0 = blockIdx.x*64;
    int tb = warp*16;

    if (tid < 64) {
        float a = g_cvec[tid];
        #pragma unroll
        for (int h = 0; h < 8; h++) a += g_cvecp[h*64+tid];
        scv[tid] = a;
    }

    ull accO0[8], accO1[8];
    #pragma unroll
    for (int pr = 0; pr < 8; pr++) { accO0[pr] = pack2(0.f,0.f); accO1[pr] = pack2(0.f,0.f); }

    for (int h = 0; h < 8; h++) {
        __syncthreads();
        for (int i = tid; i < 1024; i += 128) ws[i] = g_P4p[h*1024 + i];
        __syncthreads();

        // GEMV1: qp2[e] = sum_f xn[f]*P2[f,e] + u2[e]  (16 tokens; xn via broadcast LDG)
        float u2a = g_u2[h*64 + lane];
        float u2b = g_u2[h*64 + lane + 32];
        ull aQ0[8], aQ1[8];
        #pragma unroll
        for (int pr = 0; pr < 8; pr++) { aQ0[pr] = pack2(u2a,u2a); aQ1[pr] = pack2(u2b,u2b); }
        #pragma unroll 4
        for (int f2 = 0; f2 < 32; f2++) {
            float4 w = ws[f2*32 + lane];
            {
                ull pa0 = pack2(w.x, w.x);
                ull pa1 = pack2(w.y, w.y);
                const ulonglong2* xr = (const ulonglong2*)(g_xn + (size_t)(2*f2)*TOKENS + tok0 + tb);
                ulonglong2 x0 = xr[0], x1 = xr[1], x2 = xr[2], x3 = xr[3];
                ffma2(aQ0[0], x0.x, pa0); ffma2(aQ0[1], x0.y, pa0);
                ffma2(aQ0[2], x1.x, pa0); ffma2(aQ0[3], x1.y, pa0);
                ffma2(aQ0[4], x2.x, pa0); ffma2(aQ0[5], x2.y, pa0);
                ffma2(aQ0[6], x3.x, pa0); ffma2(aQ0[7], x3.y, pa0);
                ffma2(aQ1[0], x0.x, pa1); ffma2(aQ1[1], x0.y, pa1);
                ffma2(aQ1[2], x1.x, pa1); ffma2(aQ1[3], x1.y, pa1);
                ffma2(aQ1[4], x2.x, pa1); ffma2(aQ1[5], x2.y, pa1);
                ffma2(aQ1[6], x3.x, pa1); ffma2(aQ1[7], x3.y, pa1);
            }
            {
                ull pb0 = pack2(w.z, w.z);
                ull pb1 = pack2(w.w, w.w);
                const ulonglong2* xr = (const ulonglong2*)(g_xn + (size_t)(2*f2+1)*TOKENS + tok0 + tb);
                ulonglong2 x0 = xr[0], x1 = xr[1], x2 = xr[2], x3 = xr[3];
                ffma2(aQ0[0], x0.x, pb0); ffma2(aQ0[1], x0.y, pb0);
                ffma2(aQ0[2], x1.x, pb0); ffma2(aQ0[3], x1.y, pb0);
                ffma2(aQ0[4], x2.x, pb0); ffma2(aQ0[5], x2.y, pb0);
                ffma2(aQ0[6], x3.x, pb0); ffma2(aQ0[7], x3.y, pb0);
                ffma2(aQ1[0], x0.x, pb1); ffma2(aQ1[1], x0.y, pb1);
                ffma2(aQ1[2], x1.x, pb1); ffma2(aQ1[3], x1.y, pb1);
                ffma2(aQ1[4], x2.x, pb1); ffma2(aQ1[5], x2.y, pb1);
                ffma2(aQ1[6], x3.x, pb1); ffma2(aQ1[7], x3.y, pb1);
            }
        }
        float q0[16], q1[16];
        #pragma unroll
        for (int pr = 0; pr < 8; pr++) {
            unpack2(aQ0[pr], q0[2*pr], q0[2*pr+1]);
            unpack2(aQ1[pr], q1[2*pr], q1[2*pr+1]);
        }

        // scores + softmax + cmix (16 tokens)
        #pragma unroll 4
        for (int t = 0; t < 16; t++) {
            const float* cp = g_cls + (size_t)(tok0 + tb + t)*256 + lane;
            float c0r0 = cp[0],   c1r0 = cp[32];
            float c0r1 = cp[64],  c1r1 = cp[96];
            float c0r2 = cp[128], c1r2 = cp[160];
            float c0r3 = cp[192], c1r3 = cp[224];
            float sc0 = q0[t]*c0r0 + q1[t]*c1r0;
            float sc1 = q0[t]*c0r1 + q1[t]*c1r1;
            float sc2 = q0[t]*c0r2 + q1[t]*c1r2;
            float sc3 = q0[t]*c0r3 + q1[t]*c1r3;
            #pragma unroll
            for (int off = 16; off; off >>= 1) {
                sc0 += __shfl_xor_sync(0xffffffffu, sc0, off);
                sc1 += __shfl_xor_sync(0xffffffffu, sc1, off);
                sc2 += __shfl_xor_sync(0xffffffffu, sc2, off);
                sc3 += __shfl_xor_sync(0xffffffffu, sc3, off);
            }
            float mx = fmaxf(fmaxf(sc0,sc1), fmaxf(sc2,sc3));
            float e0 = __expf(sc0-mx), e1 = __expf(sc1-mx);
            float e2 = __expf(sc2-mx), e3 = __expf(sc3-mx);
            float inv = 1.f/(e0+e1+e2+e3);
            float a0 = e0*inv, a1 = e1*inv, a2 = e2*inv, a3 = e3*inv;
            scmix[lane*XS + tb + t]      = a0*c0r0 + a1*c0r1 + a2*c0r2 + a3*c0r3;
            scmix[(lane+32)*XS + tb + t] = a0*c1r0 + a1*c1r1 + a2*c1r2 + a3*c1r3;
        }

        __syncthreads();   // GEMV1 done reading ws(P); scmix warp-private
        for (int i = tid; i < 1024; i += 128) ws[i] = g_Q4p[h*1024 + i];
        __syncthreads();

        // GEMV2: out[o] += sum_e cmix[e]*Q2[e,o]
        #pragma unroll 4
        for (int e2 = 0; e2 < 32; e2++) {
            float4 w = ws[e2*32 + lane];
            {
                ull pa0 = pack2(w.x, w.x);
                ull pa1 = pack2(w.y, w.y);
                const ulonglong2* mr = (const ulonglong2*)(scmix + (2*e2)*XS + tb);
                ulonglong2 m0 = mr[0], m1 = mr[1], m2 = mr[2], m3 = mr[3];
                ffma2(accO0[0], m0.x, pa0); ffma2(accO0[1], m0.y, pa0);
                ffma2(accO0[2], m1.x, pa0); ffma2(accO0[3], m1.y, pa0);
                ffma2(accO0[4], m2.x, pa0); ffma2(accO0[5], m2.y, pa0);
                ffma2(accO0[6], m3.x, pa0); ffma2(accO0[7], m3.y, pa0);
                ffma2(accO1[0], m0.x, pa1); ffma2(accO1[1], m0.y, pa1);
                ffma2(accO1[2], m1.x, pa1); ffma2(accO1[3], m1.y, pa1);
                ffma2(accO1[4], m2.x, pa1); ffma2(accO1[5], m2.y, pa1);
                ffma2(accO1[6], m3.x, pa1); ffma2(accO1[7], m3.y, pa1);
            }
            {
                ull pb0 = pack2(w.z, w.z);
                ull pb1 = pack2(w.w, w.w);
                const ulonglong2* mr = (const ulonglong2*)(scmix + (2*e2+1)*XS + tb);
                ulonglong2 m0 = mr[0], m1 = mr[1], m2 = mr[2], m3 = mr[3];
                ffma2(accO0[0], m0.x, pb0); ffma2(accO0[1], m0.y, pb0);
                ffma2(accO0[2], m1.x, pb0); ffma2(accO0[3], m1.y, pb0);
                ffma2(accO0[4], m2.x, pb0); ffma2(accO0[5], m2.y, pb0);
                ffma2(accO0[6], m3.x, pb0); ffma2(accO0[7], m3.y, pb0);
                ffma2(accO1[0], m0.x, pb1); ffma2(accO1[1], m0.y, pb1);
                ffma2(accO1[2], m1.x, pb1); ffma2(accO1[3], m1.y, pb1);
                ffma2(accO1[4], m2.x, pb1); ffma2(accO1[5], m2.y, pb1);
                ffma2(accO1[6], m3.x, pb1); ffma2(accO1[7], m3.y, pb1);
            }
        }
    }

    float o0[16], o1[16];
    #pragma unroll
    for (int pr = 0; pr < 8; pr++) {
        unpack2(accO0[pr], o0[2*pr], o0[2*pr+1]);
        unpack2(accO1[pr], o1[2*pr], o1[2*pr+1]);
    }
    float c0 = scv[lane], c1 = scv[lane+32];
    #pragma unroll
    for (int t = 0; t < 16; t++) {
        outp[(size_t)(tok0+tb+t)*64 + lane]      = o0[t] + c0;
        outp[(size_t)(tok0+tb+t)*64 + lane + 32] = o1[t] + c1;
    }
}

// ---------------- launch ----------------
extern "C" void kernel_launch(void* const* d_in, const int* in_sizes, int n_in,
                              void* d_out, int out_size)
{
    const float* x      = (const float*)d_in[0];
    const float* ln_g   = (const float*)d_in[1];
    const float* ln_b   = (const float*)d_in[2];
    const float* Wqkv   = (const float*)d_in[3];
    const float* bqkv   = (const float*)d_in[4];
    const float* cls_t  = (const float*)d_in[5];
    const float* Wwqkv  = (const float*)d_in[6];
    const float* bwqkv  = (const float*)d_in[7];
    const float* Wwproj = (const float*)d_in[8];
    const float* bwproj = (const float*)d_in[9];
    const float* Wraq   = (const float*)d_in[10];
    const float* Wrak   = (const float*)d_in[11];
    const float* Wrav   = (const float*)d_in[12];
    const float* Wrao   = (const float*)d_in[13];
    const float* brao   = (const float*)d_in[14];
    const float* Wout   = (const float*)d_in[15];
    const float* bout   = (const float*)d_in[16];
    float* outp = (float*)d_out;

    int pre_smem  = 3*SBUF*4;                  // 49920 B
    int quad_smem = 9*QCH*4;                   // 84672 B
    int epi_smem  = 64*XS*4 + 1024*16;         // 17408 + 16384 = 33792 B
    cudaFuncSetAttribute(precomp, cudaFuncAttributeMaxDynamicSharedMemorySize, pre_smem);
    cudaFuncSetAttribute(k_quad,  cudaFuncAttributeMaxDynamicSharedMemorySize, quad_smem);
    cudaFuncSetAttribute(k_epi,   cudaFuncAttributeMaxDynamicSharedMemorySize, epi_smem);

    precomp<<<17, 256, pre_smem>>>(cls_t, Wwqkv, bwqkv, brao, Wout, bout,
                                   Wraq, Wrak, Wrao, Wrav, Wqkv, bqkv, Wwproj, bwproj);
    k_ln<<<TOKENS/64, 256>>>(x, ln_g, ln_b, Wwqkv, bwqkv);
    k_quad<<<BB*NHEADS, 512, quad_smem>>>();
    k_epi<<<TOKENS/64, 128, epi_smem>>>(outp);
}

// round 8
// speedup vs baseline: 1.1519x; 1.1519x over previous
#include <cuda_runtime.h>
#include <math.h>

#define BB 64
#define NTOK 2304
#define DD 64
#define NHEADS 8
#define TOKENS (BB*NTOK)   // 147456

// ---------------- scratch (device globals; no allocations) ----------------
__device__ float g_xn[TOKENS*DD];                // [token][d]
__device__ float g_v[TOKENS*DD];                 // head-major: [(b*8+h)*2304 + p]*8 + j
__device__ float g_logits[BB*NHEADS*NTOK];
__device__ float g_cls[(size_t)TOKENS*4*DD];     // [tok][r][64e]
__device__ float g_WL[NHEADS*DD];
__device__ float g_bL[NHEADS];
__device__ float g_vc[DD];
__device__ float g_clslogit[NHEADS];
__device__ float g_cvec[DD];
__device__ float g_cvecp[NHEADS*DD];             // per-head bwproj fold
__device__ float4 g_P4p[NHEADS*1024];   // [h][f2][lane] = (P2[2f2][l],P2[2f2][l+32],P2[2f2+1][l],P2[2f2+1][l+32])
__device__ float4 g_Q4p[NHEADS*1024];   // [h][e2][lane] = (Q2[2e2][l],Q2[2e2][l+32],Q2[2e2+1][l],Q2[2e2+1][l+32])
__device__ float g_u2[NHEADS*DD];

__device__ __forceinline__ float kscale() { return 0.35355339059327373f; } // 8^-0.5

// ---------------- f32x2 helpers ----------------
typedef unsigned long long ull;
__device__ __forceinline__ ull pack2(float x, float y) {
    ull r; asm("mov.b64 %0, {%1,%2};" : "=l"(r) : "f"(x), "f"(y)); return r;
}
__device__ __forceinline__ void unpack2(ull v, float& x, float& y) {
    asm("mov.b64 {%0,%1}, %2;" : "=f"(x), "=f"(y) : "l"(v));
}
__device__ __forceinline__ void ffma2(ull& acc, ull a, ull b) {
    asm("fma.rn.f32x2 %0, %1, %2, %0;" : "+l"(acc) : "l"(a), "l"(b));
}

#define SBUF 4160   // padded 64x64 buffer (allows 65-stride layouts)

// ---------------- single precompute kernel: 17 blocks ----------------
__global__ void __launch_bounds__(256) precomp(
    const float* __restrict__ cls_tok,
    const float* __restrict__ Wwqkv, const float* __restrict__ bwqkv,
    const float* __restrict__ brao,
    const float* __restrict__ Wout, const float* __restrict__ bout,
    const float* __restrict__ Wraq, const float* __restrict__ Wrak,
    const float* __restrict__ Wrao, const float* __restrict__ Wrav,
    const float* __restrict__ Wqkv, const float* __restrict__ bqkv,
    const float* __restrict__ Wwproj, const float* __restrict__ bwproj)
{
    extern __shared__ float s[];
    float* s0 = s;
    float* s1 = s + SBUF;
    float* s2 = s + 2*SBUF;
    int bid = blockIdx.x, tid = threadIdx.x;

    if (bid == 0) {
        __shared__ float scq[192];
        __shared__ float sqc[64];
        __shared__ float sred[256];
        if (tid < 192) {
            float a = bwqkv[tid];
            for (int d = 0; d < 64; d++) a += Wwqkv[tid*64+d]*cls_tok[d];
            scq[tid] = a;
        }
        __syncthreads();
        if (tid < 64) { sqc[tid] = scq[tid]*kscale(); g_vc[tid] = scq[128+tid]; }
        __syncthreads();
        if (tid < 8) {
            float cl = 0.f, bl = 0.f;
            for (int j = 0; j < 8; j++) {
                cl += sqc[tid*8+j]*scq[64+tid*8+j];
                bl += sqc[tid*8+j]*bwqkv[64+tid*8+j];
            }
            g_clslogit[tid] = cl; g_bL[tid] = bl;
        }
        for (int i = tid; i < 512; i += 256) {
            int h = i>>6, d = i&63;
            float a = 0.f;
            for (int j = 0; j < 8; j++) a += sqc[h*8+j]*Wwqkv[(64+h*8+j)*64+d];
            g_WL[i] = a;
        }
        {
            int o = tid>>2, q = tid&3;
            float a = (q==0) ? bout[o] : 0.f;
            for (int k = q*128; k < q*128+128; k++) a += Wout[o*512+k]*brao[k&63];
            sred[tid] = a;
        }
        __syncthreads();
        if (tid < 64)
            g_cvec[tid] = sred[4*tid] + sred[4*tid+1] + sred[4*tid+2] + sred[4*tid+3];
    }
    else if (bid <= 8) {
        // ---- P side: G = Wraq^T Wrak ; P = scale*Wq_h^T G ; P2 = P Wwproj ----
        int h = bid - 1;
        __shared__ float su[64];
        for (int i = tid; i < 4096; i += 256) { s0[i] = Wraq[i]; s1[i] = Wrak[i]; }
        __syncthreads();
        for (int i = tid; i < 4096; i += 256) {           // G[dd][g] -> s2
            int dd = i>>6, g = i&63;
            float a = 0.f;
            #pragma unroll 8
            for (int e = 0; e < 64; e++) a += s0[e*64+dd]*s1[e*64+g];
            s2[i] = a;
        }
        __syncthreads();
        for (int i = tid; i < 4096; i += 256) s0[i] = Wqkv[h*4096 + i];   // Wq[dd][f]
        __syncthreads();
        for (int i = tid; i < 4096; i += 256) {           // P[f][g] -> s1
            int f = i>>6, g = i&63;
            float a = 0.f;
            #pragma unroll 8
            for (int dd = 0; dd < 64; dd++) a += s0[dd*64+f]*s2[dd*64+g];
            s1[i] = a*kscale();
        }
        if (tid < 64) {                                    // u[g]
            float a = 0.f;
            for (int dd = 0; dd < 64; dd++) a += bqkv[h*64+dd]*s2[dd*64+tid];
            su[tid] = a*kscale();
        }
        __syncthreads();
        for (int i = tid; i < 4096; i += 256) s0[i] = Wwproj[i];   // W[g][e]
        __syncthreads();
        for (int i = tid; i < 4096; i += 256) {           // P2[f][e] -> s2
            int f = i>>6, e = i&63;
            float a = 0.f;
            #pragma unroll 8
            for (int g = 0; g < 64; g++) a += s1[f*64+g]*s0[g*64+e];
            s2[i] = a;
        }
        if (tid < 64) {                                    // u2[e]
            float a = 0.f;
            for (int g = 0; g < 64; g++) a += su[g]*s0[g*64+tid];
            g_u2[h*64+tid] = a;
        }
        __syncthreads();
        for (int i = tid; i < 1024; i += 256) {            // pack
            int k2 = i>>5, l = i&31;
            g_P4p[h*1024+i] = make_float4(s2[(2*k2)*64+l],   s2[(2*k2)*64+l+32],
                                          s2[(2*k2+1)*64+l], s2[(2*k2+1)*64+l+32]);
        }
    }
    else {
        // ---- Q side: R = Wrao Wrav ; Q_h = Wout_h R ; Q2 = Wwproj^T Q ----
        int h = bid - 9;
        for (int i = tid; i < 4096; i += 256) { s0[i] = Wrao[i]; s1[i] = Wrav[i]; }
        __syncthreads();
        for (int i = tid; i < 4096; i += 256) {           // R[a][g] -> s2
            int a_ = i>>6, g = i&63;
            float a = 0.f;
            #pragma unroll 8
            for (int c = 0; c < 64; c++) a += s0[a_*64+c]*s1[c*64+g];
            s2[i] = a;
        }
        __syncthreads();
        for (int i = tid; i < 4096; i += 256) {           // Wout_h[o][a]
            int o = i>>6, a_ = i&63;
            s0[i] = Wout[o*512 + h*64 + a_];
        }
        __syncthreads();
        for (int i = tid; i < 4096; i += 256) {           // Qt[o][g] -> s1
            int o = i>>6, g = i&63;
            float a = 0.f;
            #pragma unroll 8
            for (int a_ = 0; a_ < 64; a_++) a += s0[o*64+a_]*s2[a_*64+g];
            s1[i] = a;
        }
        __syncthreads();
        if (tid < 64) {                                    // cvecp[h][o]
            float a = 0.f;
            for (int g = 0; g < 64; g++) a += bwproj[g]*s1[tid*64+g];
            g_cvecp[h*64+tid] = a;
        }
        for (int i = tid; i < 4096; i += 256) s0[i] = Wwproj[i];   // W[g][e]
        __syncthreads();
        for (int i = tid; i < 4096; i += 256) {           // Q2t[o][e] -> s2 (65-stride)
            int o = i>>6, e = i&63;
            float a = 0.f;
            #pragma unroll 8
            for (int g = 0; g < 64; g++) a += s0[g*64+e]*s1[o*64+g];
            s2[o*65+e] = a;
        }
        __syncthreads();
        for (int i = tid; i < 1024; i += 256) {            // pack: Q2[e][o] = s2[o*65+e]
            int k2 = i>>5, l = i&31;
            g_Q4p[h*1024+i] = make_float4(s2[l*65 + 2*k2],      s2[(l+32)*65 + 2*k2],
                                          s2[l*65 + 2*k2 + 1],  s2[(l+32)*65 + 2*k2 + 1]);
        }
    }
}

// ---------------- K1: LayerNorm + logits + v projection (64 tokens/block) ----------------
__global__ void __launch_bounds__(256) k_ln(const float* __restrict__ x,
     const float* __restrict__ ln_g, const float* __restrict__ ln_b,
     const float* __restrict__ Wwqkv, const float* __restrict__ bwqkv)
{
    __shared__ float sfv[64*66];     // pairs (Wwv[e][d], Wwv[e+32][d]) at [d*66 + 2*(e&31) + (e>>5)]
    __shared__ float sWL[8*65];
    __shared__ float sxb[8*64];
    int tid = threadIdx.x, warp = tid>>5, lane = tid&31;
    for (int i = tid; i < 4096; i += 256) {
        int e = i>>6, d = i&63;
        sfv[d*66 + 2*(e&31) + (e>>5)] = Wwqkv[8192 + i];
    }
    for (int i = tid; i < 512; i += 256)
        sWL[(i>>6)*65 + (i&63)] = g_WL[i];
    __syncthreads();
    float ga0 = ln_g[lane], ga1 = ln_g[lane+32];
    float gb0 = ln_b[lane], gb1 = ln_b[lane+32];
    float bv0 = bwqkv[128+lane], bv1 = bwqkv[128+lane+32];
    int tok_base = blockIdx.x*64 + warp*8;
    int b = tok_base/NTOK;       // block never crosses batch
    int hh = lane>>2, qq = lane&3;
    for (int t = 0; t < 8; t++) {
        int token = tok_base + t;
        float x0 = x[token*64 + lane];
        float x1 = x[token*64 + lane + 32];
        float s = x0 + x1, ss = x0*x0 + x1*x1;
        #pragma unroll
        for (int off = 16; off; off >>= 1) {
            s  += __shfl_xor_sync(0xffffffffu, s,  off);
            ss += __shfl_xor_sync(0xffffffffu, ss, off);
        }
        float mu = s*(1.f/64.f);
        float var = ss*(1.f/64.f) - mu*mu;
        float rstd = rsqrtf(var + 1e-5f);
        float xn0 = (x0-mu)*rstd*ga0 + gb0;
        float xn1 = (x1-mu)*rstd*ga1 + gb1;
        g_xn[(size_t)token*64+lane] = xn0;
        g_xn[(size_t)token*64+lane+32] = xn1;
        sxb[warp*64+lane] = xn0; sxb[warp*64+lane+32] = xn1;
        __syncwarp();
        ull acc = pack2(bv0, bv1);
        #pragma unroll 8
        for (int d = 0; d < 64; d++) {
            float xd = sxb[warp*64+d];
            float2 w = *(const float2*)(sfv + d*66 + 2*lane);
            ffma2(acc, pack2(xd, xd), pack2(w.x, w.y));
        }
        float v0, v1; unpack2(acc, v0, v1);
        int nn = token - b*NTOK;
        {
            int h0 = lane>>3, j0 = lane&7;
            g_v[((size_t)(b*8+h0)*NTOK + nn)*8 + j0] = v0;
            int h1 = (lane+32)>>3;
            g_v[((size_t)(b*8+h1)*NTOK + nn)*8 + j0] = v1;
        }
        {
            float a = 0.f;
            #pragma unroll
            for (int dd = 0; dd < 16; dd++)
                a += sxb[warp*64 + qq*16 + dd]*sWL[hh*65 + qq*16 + dd];
            a += __shfl_xor_sync(0xffffffffu, a, 1);
            a += __shfl_xor_sync(0xffffffffu, a, 2);
            if (qq == 0) g_logits[(b*8+hh)*NTOK + nn] = a + g_bL[hh];
        }
        __syncwarp();
    }
}

// ---------------- K2: max + exp + integral-image quad sums + cls_out ----------------
#define QCH 2352   // 48*49
__global__ void __launch_bounds__(512) k_quad()
{
    extern __shared__ float s[];  // 9 * 2352 floats
    __shared__ float red[512];
    __shared__ float smv;
    int bid = blockIdx.x, tid = threadIdx.x;
    int b = bid>>3, h = bid&7;
    for (int p = tid; p < 2304; p += 512) {
        int y = p/48, xx = p - y*48;
        s[y*49+xx] = g_logits[bid*NTOK + p];
    }
    __syncthreads();
    float mloc = -1e30f;
    for (int p = tid; p < 2304; p += 512) {
        int y = p/48, xx = p - y*48;
        mloc = fmaxf(mloc, s[y*49+xx]);
    }
    red[tid] = mloc;
    __syncthreads();
    for (int st = 256; st; st >>= 1) {
        if (tid < st) red[tid] = fmaxf(red[tid], red[tid+st]);
        __syncthreads();
    }
    if (tid == 0) smv = fmaxf(red[0], g_clslogit[h]);
    __syncthreads();
    float m = smv;
    float ecls = __expf(g_clslogit[h] - m);
    for (int p = tid; p < 2304; p += 512) {
        int y = p/48, xx = p - y*48;
        int idx = y*49+xx;
        s[idx] = __expf(s[idx] - m);
    }
    __syncthreads();
    const float* vbase = g_v + (size_t)bid*NTOK*8;
    for (int i = tid; i < 2304*8; i += 512) {
        int p = i>>3, j = i&7;
        int y = p/48, xx = p - y*48;
        s[(1+j)*QCH + y*49+xx] = s[y*49+xx] * vbase[i];
    }
    __syncthreads();
    for (int sid = tid; sid < 432; sid += 512) {
        int ch = sid/48, y = sid - (sid/48)*48;
        float* row = s + ch*QCH + y*49;
        float a = 0.f;
        #pragma unroll 8
        for (int xx = 0; xx < 48; xx++) { a += row[xx]; row[xx] = a; }
    }
    __syncthreads();
    for (int sid = tid; sid < 432; sid += 512) {
        int ch = sid/48, xx = sid - (sid/48)*48;
        float* col = s + ch*QCH + xx;
        float a = 0.f;
        #pragma unroll 8
        for (int y = 0; y < 48; y++) { a += col[y*49]; col[y*49] = a; }
    }
    __syncthreads();
    float vc[8];
    #pragma unroll
    for (int j = 0; j < 8; j++) vc[j] = g_vc[h*8+j];
    for (int p = tid; p < 2304; p += 512) {
        int y = p/48, xx = p - y*48;
        int iC  = y*49 + xx;
        int iRT = y*49 + 47;
        int iCB = 47*49 + xx;
        int iT  = 47*49 + 47;
        int iCm = iC - 1;
        int iUp = iC - 49;
        int iUR = iRT - 49;
        int iCL = iCB - 1;
        int iUL = iUp - 1;
        bool hx = xx > 0, hy = y > 0;
        float rd[4];
        {
            const float* C = s;
            float tl = C[iC];
            float tr = C[iRT] - (hx ? C[iCm] : 0.f);
            float bl = C[iCB] - (hy ? C[iUp] : 0.f);
            float br = C[iT] - (hy ? C[iUR] : 0.f) - (hx ? C[iCL] : 0.f) + ((hx&&hy) ? C[iUL] : 0.f);
            rd[0] = 1.f/(ecls+tl); rd[1] = 1.f/(ecls+tr);
            rd[2] = 1.f/(ecls+bl); rd[3] = 1.f/(ecls+br);
        }
        float out[4][8];
        #pragma unroll
        for (int j = 0; j < 8; j++) {
            const float* C = s + (1+j)*QCH;
            float tl = C[iC];
            float tr = C[iRT] - (hx ? C[iCm] : 0.f);
            float bl = C[iCB] - (hy ? C[iUp] : 0.f);
            float br = C[iT] - (hy ? C[iUR] : 0.f) - (hx ? C[iCL] : 0.f) + ((hx&&hy) ? C[iUL] : 0.f);
            float base = ecls*vc[j];
            out[0][j] = (base+tl)*rd[0];
            out[1][j] = (base+tr)*rd[1];
            out[2][j] = (base+bl)*rd[2];
            out[3][j] = (base+br)*rd[3];
        }
        float* op = g_cls + ((size_t)(b*NTOK + p)*4)*64 + h*8;
        #pragma unroll
        for (int r = 0; r < 4; r++) {
            float4 v0 = make_float4(out[r][0], out[r][1], out[r][2], out[r][3]);
            float4 v1 = make_float4(out[r][4], out[r][5], out[r][6], out[r][7]);
            *(float4*)(op + r*64)     = v0;
            *(float4*)(op + r*64 + 4) = v1;
        }
    }
}

// ---------------- K3: fused epilogue (R5 config + buffered scmix stores) ----------------
// 256 threads = 8 warps; 8 tokens/warp; 64 tokens/block.
#define XS 68
__global__ void __launch_bounds__(256) k_epi(float* __restrict__ outp)
{
    extern __shared__ float s[];
    float*  sxn   = s;               // [64 f][XS]
    float*  scmix = s + 64*XS;       // [64 e][XS]
    float4* wsP4  = (float4*)(s + 2*64*XS);   // [32 f2][32 lane]
    float4* wsQ4  = wsP4 + 1024;              // [32 e2][32 lane]
    __shared__ float scv[64];
    int tid = threadIdx.x, warp = tid>>5, lane = tid&31;
    int tok0 = blockIdx.x*64;
    int tb = warp*8;

    if (tid < 64) {
        float a = g_cvec[tid];
        #pragma unroll
        for (int h = 0; h < 8; h++) a += g_cvecp[h*64+tid];
        scv[tid] = a;
    }
    for (int i = tid; i < 4096; i += 256) {
        int t = i>>6, d = i&63;
        sxn[d*XS + t] = g_xn[(size_t)(tok0+t)*64 + d];
    }

    ull accO[2][4];
    #pragma unroll
    for (int e = 0; e < 2; e++)
        #pragma unroll
        for (int pr = 0; pr < 4; pr++) accO[e][pr] = pack2(0.f, 0.f);

    for (int h = 0; h < 8; h++) {
        __syncthreads();
        for (int i = tid; i < 1024; i += 256) {
            wsP4[i] = g_P4p[h*1024 + i];
            wsQ4[i] = g_Q4p[h*1024 + i];
        }
        __syncthreads();

        // GEMV1: qp2[e] = sum_f xn[f]*P2[f,e] + u2[e]
        float u2a = g_u2[h*64 + lane];
        float u2b = g_u2[h*64 + lane + 32];
        ull aQ[2][4];
        #pragma unroll
        for (int pr = 0; pr < 4; pr++) { aQ[0][pr] = pack2(u2a,u2a); aQ[1][pr] = pack2(u2b,u2b); }
        #pragma unroll 8
        for (int f2 = 0; f2 < 32; f2++) {
            float4 w = wsP4[f2*32 + lane];
            ull pa0 = pack2(w.x, w.x);
            ull pa1 = pack2(w.y, w.y);
            ull pb0 = pack2(w.z, w.z);
            ull pb1 = pack2(w.w, w.w);
            const ulonglong2* xr0 = (const ulonglong2*)(sxn + (2*f2)*XS + tb);
            const ulonglong2* xr1 = (const ulonglong2*)(sxn + (2*f2+1)*XS + tb);
            ulonglong2 xa = xr0[0], xb = xr0[1];
            ulonglong2 xc = xr1[0], xd = xr1[1];
            ffma2(aQ[0][0], xa.x, pa0); ffma2(aQ[0][1], xa.y, pa0);
            ffma2(aQ[0][2], xb.x, pa0); ffma2(aQ[0][3], xb.y, pa0);
            ffma2(aQ[1][0], xa.x, pa1); ffma2(aQ[1][1], xa.y, pa1);
            ffma2(aQ[1][2], xb.x, pa1); ffma2(aQ[1][3], xb.y, pa1);
            ffma2(aQ[0][0], xc.x, pb0); ffma2(aQ[0][1], xc.y, pb0);
            ffma2(aQ[0][2], xd.x, pb0); ffma2(aQ[0][3], xd.y, pb0);
            ffma2(aQ[1][0], xc.x, pb1); ffma2(aQ[1][1], xc.y, pb1);
            ffma2(aQ[1][2], xd.x, pb1); ffma2(aQ[1][3], xd.y, pb1);
        }
        float q0[8], q1[8];
        #pragma unroll
        for (int pr = 0; pr < 4; pr++) {
            unpack2(aQ[0][pr], q0[2*pr], q0[2*pr+1]);
            unpack2(aQ[1][pr], q1[2*pr], q1[2*pr+1]);
        }

        // scores + softmax + cmix (float2-buffered stores: 2 tokens per STS.64)
        float mb0[2], mb1[2];
        #pragma unroll
        for (int t = 0; t < 8; t++) {
            const float* cp = g_cls + (size_t)(tok0 + tb + t)*256 + lane;
            float c0r0 = cp[0],   c1r0 = cp[32];
            float c0r1 = cp[64],  c1r1 = cp[96];
            float c0r2 = cp[128], c1r2 = cp[160];
            float c0r3 = cp[192], c1r3 = cp[224];
            float sc0 = q0[t]*c0r0 + q1[t]*c1r0;
            float sc1 = q0[t]*c0r1 + q1[t]*c1r1;
            float sc2 = q0[t]*c0r2 + q1[t]*c1r2;
            float sc3 = q0[t]*c0r3 + q1[t]*c1r3;
            #pragma unroll
            for (int off = 16; off; off >>= 1) {
                sc0 += __shfl_xor_sync(0xffffffffu, sc0, off);
                sc1 += __shfl_xor_sync(0xffffffffu, sc1, off);
                sc2 += __shfl_xor_sync(0xffffffffu, sc2, off);
                sc3 += __shfl_xor_sync(0xffffffffu, sc3, off);
            }
            float mx = fmaxf(fmaxf(sc0,sc1), fmaxf(sc2,sc3));
            float e0 = __expf(sc0-mx), e1 = __expf(sc1-mx);
            float e2 = __expf(sc2-mx), e3 = __expf(sc3-mx);
            float inv = 1.f/(e0+e1+e2+e3);
            float a0 = e0*inv, a1 = e1*inv, a2 = e2*inv, a3 = e3*inv;
            mb0[t&1] = a0*c0r0 + a1*c0r1 + a2*c0r2 + a3*c0r3;
            mb1[t&1] = a0*c1r0 + a1*c1r1 + a2*c1r2 + a3*c1r3;
            if (t & 1) {
                *(float2*)(scmix + lane*XS + tb + t - 1)      = make_float2(mb0[0], mb0[1]);
                *(float2*)(scmix + (lane+32)*XS + tb + t - 1) = make_float2(mb1[0], mb1[1]);
            }
        }
        __syncwarp();

        // GEMV2: out[o] += sum_e cmix[e]*Q2[e,o]
        #pragma unroll 8
        for (int e2 = 0; e2 < 32; e2++) {
            float4 w = wsQ4[e2*32 + lane];
            ull pa0 = pack2(w.x, w.x);
            ull pa1 = pack2(w.y, w.y);
            ull pb0 = pack2(w.z, w.z);
            ull pb1 = pack2(w.w, w.w);
            const ulonglong2* mr0 = (const ulonglong2*)(scmix + (2*e2)*XS + tb);
            const ulonglong2* mr1 = (const ulonglong2*)(scmix + (2*e2+1)*XS + tb);
            ulonglong2 ma = mr0[0], mb = mr0[1];
            ulonglong2 mc = mr1[0], md = mr1[1];
            ffma2(accO[0][0], ma.x, pa0); ffma2(accO[0][1], ma.y, pa0);
            ffma2(accO[0][2], mb.x, pa0); ffma2(accO[0][3], mb.y, pa0);
            ffma2(accO[1][0], ma.x, pa1); ffma2(accO[1][1], ma.y, pa1);
            ffma2(accO[1][2], mb.x, pa1); ffma2(accO[1][3], mb.y, pa1);
            ffma2(accO[0][0], mc.x, pb0); ffma2(accO[0][1], mc.y, pb0);
            ffma2(accO[0][2], md.x, pb0); ffma2(accO[0][3], md.y, pb0);
            ffma2(accO[1][0], mc.x, pb1); ffma2(accO[1][1], mc.y, pb1);
            ffma2(accO[1][2], md.x, pb1); ffma2(accO[1][3], md.y, pb1);
        }
    }

    float o0[8], o1[8];
    #pragma unroll
    for (int pr = 0; pr < 4; pr++) {
        unpack2(accO[0][pr], o0[2*pr], o0[2*pr+1]);
        unpack2(accO[1][pr], o1[2*pr], o1[2*pr+1]);
    }
    float c0 = scv[lane], c1 = scv[lane+32];
    #pragma unroll
    for (int t = 0; t < 8; t++) {
        outp[(size_t)(tok0+tb+t)*64 + lane]      = o0[t] + c0;
        outp[(size_t)(tok0+tb+t)*64 + lane + 32] = o1[t] + c1;
    }
}

// ---------------- launch ----------------
extern "C" void kernel_launch(void* const* d_in, const int* in_sizes, int n_in,
                              void* d_out, int out_size)
{
    const float* x      = (const float*)d_in[0];
    const float* ln_g   = (const float*)d_in[1];
    const float* ln_b   = (const float*)d_in[2];
    const float* Wqkv   = (const float*)d_in[3];
    const float* bqkv   = (const float*)d_in[4];
    const float* cls_t  = (const float*)d_in[5];
    const float* Wwqkv  = (const float*)d_in[6];
    const float* bwqkv  = (const float*)d_in[7];
    const float* Wwproj = (const float*)d_in[8];
    const float* bwproj = (const float*)d_in[9];
    const float* Wraq   = (const float*)d_in[10];
    const float* Wrak   = (const float*)d_in[11];
    const float* Wrav   = (const float*)d_in[12];
    const float* Wrao   = (const float*)d_in[13];
    const float* brao   = (const float*)d_in[14];
    const float* Wout   = (const float*)d_in[15];
    const float* bout   = (const float*)d_in[16];
    float* outp = (float*)d_out;

    int pre_smem  = 3*SBUF*4;                  // 49920 B
    int quad_smem = 9*QCH*4;                   // 84672 B
    int epi_smem  = (2*64*XS)*4 + 2*1024*16;   // 34816 + 32768 = 67584 B
    cudaFuncSetAttribute(precomp, cudaFuncAttributeMaxDynamicSharedMemorySize, pre_smem);
    cudaFuncSetAttribute(k_quad,  cudaFuncAttributeMaxDynamicSharedMemorySize, quad_smem);
    cudaFuncSetAttribute(k_epi,   cudaFuncAttributeMaxDynamicSharedMemorySize, epi_smem);

    precomp<<<17, 256, pre_smem>>>(cls_t, Wwqkv, bwqkv, brao, Wout, bout,
                                   Wraq, Wrak, Wrao, Wrav, Wqkv, bqkv, Wwproj, bwproj);
    k_ln<<<TOKENS/64, 256>>>(x, ln_g, ln_b, Wwqkv, bwqkv);
    k_quad<<<BB*NHEADS, 512, quad_smem>>>();
    k_epi<<<TOKENS/64, 256, epi_smem>>>(outp);
}